// round 2
// baseline (speedup 1.0000x reference)
#include <cuda_runtime.h>
#include <math.h>
#include <float.h>

#define DDEPTH 7
#define IND   128
#define GRIDN 128
#define HIDN  256
#define BATCHN 2048
#define NT    129          // t in 0..128
#define TROW  (HIDN * 2)   // 512 floats per table row: (P1,P2) interleaved per h

// ---------------- scratch (static device memory; no allocation) ----------------
__device__ float g_xmin[IND];
__device__ float g_xmax[IND];
__device__ float g_Z[BATCHN * IND];
__device__ float g_sg[DDEPTH * IND * GRIDN];     // sorted grids
__device__ int   g_perm[DDEPTH * IND * GRIDN];   // permutation into original g index
__device__ float g_T[(size_t)DDEPTH * IND * NT * TROW];   // 236.7 MB prefix tables
__device__ unsigned char g_tmap[(size_t)DDEPTH * IND * BATCHN];
__device__ float g_Ha[BATCHN * HIDN];
__device__ float g_Hb[BATCHN * HIDN];
__device__ double g_sum[HIDN];
__device__ double g_sumsq[HIDN];
__device__ float2 g_bnp[HIDN];

// ---------------- 1. per-feature min/max over batch ----------------
__global__ void k_minmax(const float* __restrict__ x) {
    int i = blockIdx.x;
    float mn = FLT_MAX, mx = -FLT_MAX;
    for (int b = threadIdx.x; b < BATCHN; b += blockDim.x) {
        float v = x[b * IND + i];
        mn = fminf(mn, v);
        mx = fmaxf(mx, v);
    }
    __shared__ float smn[256], smx[256];
    smn[threadIdx.x] = mn; smx[threadIdx.x] = mx;
    __syncthreads();
    for (int s = 128; s > 0; s >>= 1) {
        if (threadIdx.x < s) {
            smn[threadIdx.x] = fminf(smn[threadIdx.x], smn[threadIdx.x + s]);
            smx[threadIdx.x] = fmaxf(smx[threadIdx.x], smx[threadIdx.x + s]);
        }
        __syncthreads();
    }
    if (threadIdx.x == 0) { g_xmin[i] = smn[0]; g_xmax[i] = smx[0]; }
}

// ---------------- 2. z = (x - min) / (max - min + 1e-6) ----------------
__global__ void k_z(const float* __restrict__ x) {
    int idx = blockIdx.x * blockDim.x + threadIdx.x;
    if (idx < BATCHN * IND) {
        int i = idx & (IND - 1);
        g_Z[idx] = (x[idx] - g_xmin[i]) / (g_xmax[i] - g_xmin[i] + 1e-6f);
    }
}

// ---------------- 3. sort grids per (d,i) via rank ----------------
__global__ void k_sort(const float* __restrict__ grids) {
    int di = blockIdx.x;                 // 0..895
    int t  = threadIdx.x;                // 0..127
    __shared__ float sg[GRIDN];
    float g = grids[di * GRIDN + t];
    sg[t] = g;
    __syncthreads();
    int r = 0;
    #pragma unroll 8
    for (int j = 0; j < GRIDN; j++) {
        float gj = sg[j];
        r += (gj < g) || (gj == g && j < t);
    }
    g_sg[di * GRIDN + r]   = g;
    g_perm[di * GRIDN + r] = t;
}

// ---------------- 4. prefix tables: P1 = prefix(f), P2 = prefix(g*f) ----------------
__global__ void k_table(const float* __restrict__ fs) {
    int di = blockIdx.x;
    int h  = threadIdx.x;                // 0..255
    const float* fbase = fs + (size_t)di * GRIDN * HIDN;
    float* Tb = g_T + (size_t)di * NT * TROW;
    const float* sg = g_sg + di * GRIDN;
    const int*   pm = g_perm + di * GRIDN;
    float a1 = 0.f, a2 = 0.f;
    ((float2*)Tb)[h] = make_float2(0.f, 0.f);      // t = 0 row
    for (int t = 0; t < GRIDN; t++) {
        int p    = pm[t];
        float gv = sg[t];
        float f  = fbase[p * HIDN + h];
        a1 += f;
        a2 = fmaf(gv, f, a2);
        ((float2*)(Tb + (size_t)(t + 1) * TROW))[h] = make_float2(a1, a2);
    }
}

// ---------------- 5. t[d,i,b] = #{ g < z } via branchless binary search ----------------
__global__ void k_tmap() {
    int di = blockIdx.x;
    __shared__ float sg[GRIDN];
    if (threadIdx.x < GRIDN) sg[threadIdx.x] = g_sg[di * GRIDN + threadIdx.x];
    __syncthreads();
    int i = di & (IND - 1);
    for (int b = threadIdx.x; b < BATCHN; b += blockDim.x) {
        float z = g_Z[b * IND + i];
        int t = 0;
        #pragma unroll
        for (int s = 64; s > 0; s >>= 1) {
            int nt = t + s;
            if (nt <= GRIDN && sg[nt - 1] < z) t = nt;
        }
        g_tmap[(size_t)di * BATCHN + b] = (unsigned char)t;
    }
}

// ---------------- 6. main fused gather-FMA kernel ----------------
// out_h[b,h] = sum_d c_d * sum_i ( z[b,i]*P1[d,i,t,h] - P2[d,i,t,h] )
// c_d = suffix sum of softmax(depth_scores)  (residual-depth collapse)
__global__ void __launch_bounds__(256) k_main(const float* __restrict__ ds) {
    __shared__ float         z_s[IND * 16];
    __shared__ unsigned char t_s[IND * 16];
    int tid = threadIdx.x;
    int hx  = tid & 127;    // owns h = 2*hx, 2*hx+1
    int bs  = tid >> 7;     // batch subgroup 0/1 (8 b's each)
    int b0  = blockIdx.x * 16;

    for (int idx = tid; idx < IND * 16; idx += 256) {
        int b = idx >> 7, i = idx & 127;               // coalesced over i
        z_s[i * 16 + b] = g_Z[(b0 + b) * IND + i];
    }

    // softmax + suffix weights (tiny, redundant per thread)
    float w[DDEPTH];
    float m = -FLT_MAX;
    for (int d = 0; d < DDEPTH; d++) m = fmaxf(m, ds[d]);
    float ssum = 0.f;
    for (int d = 0; d < DDEPTH; d++) { w[d] = expf(ds[d] - m); ssum += w[d]; }
    float c[DDEPTH];
    float suf = 0.f;
    for (int d = DDEPTH - 1; d >= 0; --d) { suf += w[d] / ssum; c[d] = suf; }

    float acc0[8], acc1[8];
    #pragma unroll
    for (int b = 0; b < 8; b++) { acc0[b] = 0.f; acc1[b] = 0.f; }

    __syncthreads();

    for (int d = 0; d < DDEPTH; d++) {
        for (int idx = tid; idx < IND * 16; idx += 256) {
            int i = idx >> 4, b = idx & 15;
            t_s[idx] = g_tmap[((size_t)(d * IND + i)) * BATCHN + b0 + b];
        }
        __syncthreads();
        float cd = c[d];
        for (int i = 0; i < IND; i++) {
            const float* rb = g_T + (size_t)(d * IND + i) * NT * TROW + 4 * hx;
            int sb = i * 16 + bs * 8;
            #pragma unroll
            for (int b = 0; b < 8; b++) {
                int   t  = t_s[sb + b];
                float zb = z_s[sb + b];
                float4 v = *(const float4*)(rb + t * TROW);
                float czb = cd * zb;
                acc0[b] = fmaf(czb, v.x, fmaf(-cd, v.y, acc0[b]));
                acc1[b] = fmaf(czb, v.z, fmaf(-cd, v.w, acc1[b]));
            }
        }
        __syncthreads();
    }

    #pragma unroll
    for (int b = 0; b < 8; b++) {
        int bb = b0 + bs * 8 + b;
        *(float2*)&g_Ha[bb * HIDN + 2 * hx] = make_float2(acc0[b], acc1[b]);
    }
}

// ---------------- 7. MLP head ----------------
__global__ void k_zstat() {
    int t = threadIdx.x;
    g_sum[t] = 0.0; g_sumsq[t] = 0.0;
}

// y = g_Ha @ W + bias -> g_Hb, plus batch stats (double atomics)
__global__ void __launch_bounds__(256) k_gemm(const float* __restrict__ W,
                                              const float* __restrict__ bias) {
    __shared__ float Hs[32 * HIDN];   // 32 KB
    int b0 = blockIdx.x * 32;
    int tid = threadIdx.x;            // hx = column index
    for (int idx = tid; idx < 32 * HIDN; idx += 256)
        Hs[idx] = g_Ha[b0 * HIDN + idx];
    __syncthreads();

    float acc[32];
    #pragma unroll
    for (int b = 0; b < 32; b++) acc[b] = 0.f;
    int hx = tid;
    for (int k4 = 0; k4 < HIDN / 4; k4++) {
        float w0 = W[(4 * k4 + 0) * HIDN + hx];
        float w1 = W[(4 * k4 + 1) * HIDN + hx];
        float w2 = W[(4 * k4 + 2) * HIDN + hx];
        float w3 = W[(4 * k4 + 3) * HIDN + hx];
        #pragma unroll
        for (int b = 0; b < 32; b++) {
            float4 hv = *(const float4*)&Hs[b * HIDN + 4 * k4];
            acc[b] = fmaf(hv.x, w0, fmaf(hv.y, w1, fmaf(hv.z, w2, fmaf(hv.w, w3, acc[b]))));
        }
    }
    float bsv = bias[hx];
    double s1 = 0.0, s2 = 0.0;
    #pragma unroll
    for (int b = 0; b < 32; b++) {
        float y = acc[b] + bsv;
        g_Hb[(b0 + b) * HIDN + hx] = y;
        s1 += (double)y;
        s2 += (double)y * (double)y;
    }
    atomicAdd(&g_sum[hx], s1);
    atomicAdd(&g_sumsq[hx], s2);
}

__global__ void k_bnfin(const float* __restrict__ gamma, const float* __restrict__ beta) {
    int h = threadIdx.x;
    double mean = g_sum[h] / (double)BATCHN;
    double var  = g_sumsq[h] / (double)BATCHN - mean * mean;
    float scale = gamma[h] * rsqrtf((float)var + 1e-5f);
    float shift = beta[h] - (float)mean * scale;
    g_bnp[h] = make_float2(scale, shift);
}

__global__ void k_bngelu() {
    int idx = blockIdx.x * blockDim.x + threadIdx.x;
    if (idx < BATCHN * HIDN) {
        int h = idx & (HIDN - 1);
        float2 p = g_bnp[h];
        float y = fmaf(g_Hb[idx], p.x, p.y);
        g_Ha[idx] = 0.5f * y * (1.0f + erff(y * 0.70710678118654752440f));
    }
}

__global__ void k_final(const float* __restrict__ Wout, const float* __restrict__ bout,
                        float* __restrict__ out) {
    int b = blockIdx.x * 8 + (threadIdx.x >> 5);
    int lane = threadIdx.x & 31;
    const float* hr = g_Ha + b * HIDN;
    float s = 0.f;
    #pragma unroll
    for (int k = lane; k < HIDN; k += 32) s += hr[k] * Wout[k];
    #pragma unroll
    for (int o = 16; o > 0; o >>= 1) s += __shfl_down_sync(0xffffffffu, s, o);
    if (lane == 0) out[b] = s + bout[0];
}

// ---------------- launch ----------------
extern "C" void kernel_launch(void* const* d_in, const int* in_sizes, int n_in,
                              void* d_out, int out_size) {
    const float* x     = (const float*)d_in[0];   // [2048,128]
    const float* grids = (const float*)d_in[1];   // [7,128,128]
    const float* fs    = (const float*)d_in[2];   // [7,128,128,256]
    const float* ds    = (const float*)d_in[3];   // [7]
    const float* mlpW  = (const float*)d_in[4];   // [3,256,256]
    const float* mlpb  = (const float*)d_in[5];   // [3,256]
    const float* gamma = (const float*)d_in[6];   // [3,256]
    const float* beta  = (const float*)d_in[7];   // [3,256]
    const float* Wout  = (const float*)d_in[8];   // [256,1]
    const float* bout  = (const float*)d_in[9];   // [1]
    float* out = (float*)d_out;

    k_minmax<<<IND, 256>>>(x);
    k_z<<<(BATCHN * IND + 255) / 256, 256>>>(x);
    k_sort<<<DDEPTH * IND, GRIDN>>>(grids);
    k_table<<<DDEPTH * IND, HIDN>>>(fs);
    k_tmap<<<DDEPTH * IND, 256>>>();
    k_main<<<BATCHN / 16, 256>>>(ds);

    for (int j = 0; j < 3; j++) {
        k_zstat<<<1, HIDN>>>();
        k_gemm<<<BATCHN / 32, 256>>>(mlpW + (size_t)j * HIDN * HIDN, mlpb + j * HIDN);
        k_bnfin<<<1, HIDN>>>(gamma + j * HIDN, beta + j * HIDN);
        k_bngelu<<<(BATCHN * HIDN + 511) / 512, 512>>>();
    }
    k_final<<<BATCHN / 8, 256>>>(Wout, bout, out);
}

// round 3
// speedup vs baseline: 2.3681x; 2.3681x over previous
#include <cuda_runtime.h>
#include <math.h>
#include <float.h>

#define DDEPTH 7
#define IND   128
#define GRIDN 128
#define HIDN  256
#define BATCHN 2048
#define NT    129          // t in 0..128
#define TROW  (HIDN * 2)   // 512 floats per table row: (P1,P2) interleaved per h

// ---------------- scratch (static device memory; no allocation) ----------------
__device__ float g_xmin[IND];
__device__ float g_xmax[IND];
__device__ float g_Z[BATCHN * IND];
__device__ float g_sg[DDEPTH * IND * GRIDN];     // sorted grids
__device__ int   g_perm[DDEPTH * IND * GRIDN];   // permutation into original g index
__device__ float g_T[(size_t)DDEPTH * IND * NT * TROW];   // 236.7 MB prefix tables
__device__ unsigned char g_tmap[(size_t)DDEPTH * IND * BATCHN];
__device__ float g_Ha[BATCHN * HIDN];
__device__ float g_Hb[BATCHN * HIDN];
__device__ double g_sum[HIDN];
__device__ double g_sumsq[HIDN];
__device__ float2 g_bnp[HIDN];

// ---------------- 1. per-feature min/max over batch ----------------
__global__ void k_minmax(const float* __restrict__ x) {
    int i = blockIdx.x;
    float mn = FLT_MAX, mx = -FLT_MAX;
    for (int b = threadIdx.x; b < BATCHN; b += blockDim.x) {
        float v = x[b * IND + i];
        mn = fminf(mn, v);
        mx = fmaxf(mx, v);
    }
    __shared__ float smn[256], smx[256];
    smn[threadIdx.x] = mn; smx[threadIdx.x] = mx;
    __syncthreads();
    for (int s = 128; s > 0; s >>= 1) {
        if (threadIdx.x < s) {
            smn[threadIdx.x] = fminf(smn[threadIdx.x], smn[threadIdx.x + s]);
            smx[threadIdx.x] = fmaxf(smx[threadIdx.x], smx[threadIdx.x + s]);
        }
        __syncthreads();
    }
    if (threadIdx.x == 0) { g_xmin[i] = smn[0]; g_xmax[i] = smx[0]; }
}

// ---------------- 2. z = (x - min) / (max - min + 1e-6) ----------------
__global__ void k_z(const float* __restrict__ x) {
    int idx = blockIdx.x * blockDim.x + threadIdx.x;
    if (idx < BATCHN * IND) {
        int i = idx & (IND - 1);
        g_Z[idx] = (x[idx] - g_xmin[i]) / (g_xmax[i] - g_xmin[i] + 1e-6f);
    }
}

// ---------------- 3. sort grids per (d,i) via rank ----------------
__global__ void k_sort(const float* __restrict__ grids) {
    int di = blockIdx.x;                 // 0..895
    int t  = threadIdx.x;                // 0..127
    __shared__ float sg[GRIDN];
    float g = grids[di * GRIDN + t];
    sg[t] = g;
    __syncthreads();
    int r = 0;
    #pragma unroll 8
    for (int j = 0; j < GRIDN; j++) {
        float gj = sg[j];
        r += (gj < g) || (gj == g && j < t);
    }
    g_sg[di * GRIDN + r]   = g;
    g_perm[di * GRIDN + r] = t;
}

// ---------------- 4. prefix tables: P1 = prefix(f), P2 = prefix(g*f) ----------------
// Unroll-4 with batched loads for MLP=4.
__global__ void __launch_bounds__(256) k_table(const float* __restrict__ fs) {
    __shared__ float ssg[GRIDN];
    __shared__ int   spm[GRIDN];
    int di = blockIdx.x;
    int h  = threadIdx.x;                // 0..255
    if (h < GRIDN) {
        ssg[h] = g_sg[di * GRIDN + h];
        spm[h] = g_perm[di * GRIDN + h];
    }
    __syncthreads();
    const float* fbase = fs + (size_t)di * GRIDN * HIDN;
    float* Tb = g_T + (size_t)di * NT * TROW;
    float a1 = 0.f, a2 = 0.f;
    ((float2*)Tb)[h] = make_float2(0.f, 0.f);      // t = 0 row
    for (int t0 = 0; t0 < GRIDN; t0 += 4) {
        int p0 = spm[t0 + 0], p1 = spm[t0 + 1], p2 = spm[t0 + 2], p3 = spm[t0 + 3];
        float f0 = fbase[p0 * HIDN + h];
        float f1 = fbase[p1 * HIDN + h];
        float f2 = fbase[p2 * HIDN + h];
        float f3 = fbase[p3 * HIDN + h];
        a1 += f0; a2 = fmaf(ssg[t0 + 0], f0, a2);
        ((float2*)(Tb + (size_t)(t0 + 1) * TROW))[h] = make_float2(a1, a2);
        a1 += f1; a2 = fmaf(ssg[t0 + 1], f1, a2);
        ((float2*)(Tb + (size_t)(t0 + 2) * TROW))[h] = make_float2(a1, a2);
        a1 += f2; a2 = fmaf(ssg[t0 + 2], f2, a2);
        ((float2*)(Tb + (size_t)(t0 + 3) * TROW))[h] = make_float2(a1, a2);
        a1 += f3; a2 = fmaf(ssg[t0 + 3], f3, a2);
        ((float2*)(Tb + (size_t)(t0 + 4) * TROW))[h] = make_float2(a1, a2);
    }
}

// ---------------- 5. t[d,i,b] = #{ g < z } via branchless binary search ----------------
__global__ void k_tmap() {
    int di = blockIdx.x;
    __shared__ float sg[GRIDN];
    if (threadIdx.x < GRIDN) sg[threadIdx.x] = g_sg[di * GRIDN + threadIdx.x];
    __syncthreads();
    int i = di & (IND - 1);
    for (int b = threadIdx.x; b < BATCHN; b += blockDim.x) {
        float z = g_Z[b * IND + i];
        int t = 0;
        #pragma unroll
        for (int s = 64; s > 0; s >>= 1) {
            int nt = t + s;
            if (nt <= GRIDN && sg[nt - 1] < z) t = nt;
        }
        g_tmap[(size_t)di * BATCHN + b] = (unsigned char)t;
    }
}

// ---------------- 6. main fused gather-FMA kernel ----------------
// 512 CTAs (4 batches each) x 256 threads; hx = tid&127 owns h pair (2hx, 2hx+1),
// bs = tid>>7 owns batches {bs*2, bs*2+1}. All t-maps + z staged to smem once.
// i-outer, d fully unrolled => 14 independent LDG.128 per thread per i.
__global__ void __launch_bounds__(256) k_main(const float* __restrict__ ds) {
    __shared__ float  z_s[4 * IND];          // [i][b], b fast
    __shared__ uchar4 t_s[DDEPTH * IND];     // [d*128 + i] -> t for 4 batches
    int tid = threadIdx.x;
    int hx  = tid & 127;
    int bs  = tid >> 7;     // 0 or 1
    int b0  = blockIdx.x * 4;

    for (int idx = tid; idx < 4 * IND; idx += 256) {
        int b = idx >> 7, i = idx & 127;             // coalesced over i
        z_s[i * 4 + b] = g_Z[(b0 + b) * IND + i];
    }
    for (int idx = tid; idx < DDEPTH * IND; idx += 256) {
        t_s[idx] = *(const uchar4*)&g_tmap[(size_t)idx * BATCHN + b0];
    }

    // softmax + suffix weights (tiny, redundant per thread)
    float w[DDEPTH];
    float m = -FLT_MAX;
    for (int d = 0; d < DDEPTH; d++) m = fmaxf(m, ds[d]);
    float ssum = 0.f;
    for (int d = 0; d < DDEPTH; d++) { w[d] = expf(ds[d] - m); ssum += w[d]; }
    float c[DDEPTH];
    float suf = 0.f;
    for (int d = DDEPTH - 1; d >= 0; --d) { suf += w[d] / ssum; c[d] = suf; }

    __syncthreads();

    float a00 = 0.f, a01 = 0.f, a10 = 0.f, a11 = 0.f;

    for (int i = 0; i < IND; i++) {
        float4 z4 = *(const float4*)&z_s[i * 4];
        float z0 = bs ? z4.z : z4.x;
        float z1 = bs ? z4.w : z4.y;
        const float* Ti = g_T + (size_t)i * (NT * TROW) + 4 * hx;
        #pragma unroll
        for (int d = 0; d < DDEPTH; d++) {
            uchar4 t4 = t_s[d * IND + i];
            int t0 = bs ? t4.z : t4.x;
            int t1 = bs ? t4.w : t4.y;
            const float* rb = Ti + (size_t)d * (IND * NT * TROW);
            float4 v0 = *(const float4*)(rb + t0 * TROW);
            float4 v1 = *(const float4*)(rb + t1 * TROW);
            float cd = c[d];
            float cz0 = cd * z0, cz1 = cd * z1;
            a00 = fmaf(cz0, v0.x, fmaf(-cd, v0.y, a00));
            a01 = fmaf(cz0, v0.z, fmaf(-cd, v0.w, a01));
            a10 = fmaf(cz1, v1.x, fmaf(-cd, v1.y, a10));
            a11 = fmaf(cz1, v1.z, fmaf(-cd, v1.w, a11));
        }
    }

    int bb = b0 + bs * 2;
    *(float2*)&g_Ha[(size_t)bb       * HIDN + 2 * hx] = make_float2(a00, a01);
    *(float2*)&g_Ha[(size_t)(bb + 1) * HIDN + 2 * hx] = make_float2(a10, a11);
}

// ---------------- 7. MLP head ----------------
__global__ void k_zstat() {
    int t = threadIdx.x;
    g_sum[t] = 0.0; g_sumsq[t] = 0.0;
}

__device__ __forceinline__ float gelu_exact(float y) {
    return 0.5f * y * (1.0f + erff(y * 0.70710678118654752440f));
}

// dst = act(src) @ W + bias ; act = BN(prev layer params in g_bnp) + GELU if act!=0.
// Also accumulates batch stats of dst into g_sum/g_sumsq (double atomics).
__global__ void __launch_bounds__(256) k_gemm(const float* __restrict__ W,
                                              const float* __restrict__ bias,
                                              const float* __restrict__ src,
                                              float* __restrict__ dst,
                                              int act) {
    __shared__ float Hs[16 * HIDN];   // 16 KB
    int b0 = blockIdx.x * 16;
    int tid = threadIdx.x;
    for (int idx = tid; idx < 16 * HIDN; idx += 256) {
        float v = src[(size_t)b0 * HIDN + idx];
        if (act) {
            float2 p = g_bnp[idx & (HIDN - 1)];
            v = gelu_exact(fmaf(v, p.x, p.y));
        }
        Hs[idx] = v;
    }
    __syncthreads();

    float acc[16];
    #pragma unroll
    for (int b = 0; b < 16; b++) acc[b] = 0.f;
    int hx = tid;
    for (int k4 = 0; k4 < HIDN / 4; k4++) {
        float w0 = W[(4 * k4 + 0) * HIDN + hx];
        float w1 = W[(4 * k4 + 1) * HIDN + hx];
        float w2 = W[(4 * k4 + 2) * HIDN + hx];
        float w3 = W[(4 * k4 + 3) * HIDN + hx];
        #pragma unroll
        for (int b = 0; b < 16; b++) {
            float4 hv = *(const float4*)&Hs[b * HIDN + 4 * k4];
            acc[b] = fmaf(hv.x, w0, fmaf(hv.y, w1, fmaf(hv.z, w2, fmaf(hv.w, w3, acc[b]))));
        }
    }
    float bsv = bias[hx];
    double s1 = 0.0, s2 = 0.0;
    #pragma unroll
    for (int b = 0; b < 16; b++) {
        float y = acc[b] + bsv;
        dst[(size_t)(b0 + b) * HIDN + hx] = y;
        s1 += (double)y;
        s2 += (double)y * (double)y;
    }
    atomicAdd(&g_sum[hx], s1);
    atomicAdd(&g_sumsq[hx], s2);
}

// compute BN params for the layer just produced, then re-zero stats for the next
__global__ void k_bnfin(const float* __restrict__ gamma, const float* __restrict__ beta) {
    int h = threadIdx.x;
    double mean = g_sum[h] / (double)BATCHN;
    double var  = g_sumsq[h] / (double)BATCHN - mean * mean;
    float scale = gamma[h] * rsqrtf((float)var + 1e-5f);
    float shift = beta[h] - (float)mean * scale;
    g_bnp[h] = make_float2(scale, shift);
    g_sum[h] = 0.0; g_sumsq[h] = 0.0;
}

// final: apply BN(layer2)+GELU inline, dot with W_out
__global__ void k_final(const float* __restrict__ Wout, const float* __restrict__ bout,
                        float* __restrict__ out) {
    int b = blockIdx.x * 8 + (threadIdx.x >> 5);
    int lane = threadIdx.x & 31;
    const float* hr = g_Hb + (size_t)b * HIDN;
    float s = 0.f;
    #pragma unroll
    for (int k = lane; k < HIDN; k += 32) {
        float2 p = g_bnp[k];
        float y = gelu_exact(fmaf(hr[k], p.x, p.y));
        s = fmaf(y, Wout[k], s);
    }
    #pragma unroll
    for (int o = 16; o > 0; o >>= 1) s += __shfl_down_sync(0xffffffffu, s, o);
    if (lane == 0) out[b] = s + bout[0];
}

// ---------------- launch ----------------
extern "C" void kernel_launch(void* const* d_in, const int* in_sizes, int n_in,
                              void* d_out, int out_size) {
    const float* x     = (const float*)d_in[0];   // [2048,128]
    const float* grids = (const float*)d_in[1];   // [7,128,128]
    const float* fs    = (const float*)d_in[2];   // [7,128,128,256]
    const float* ds    = (const float*)d_in[3];   // [7]
    const float* mlpW  = (const float*)d_in[4];   // [3,256,256]
    const float* mlpb  = (const float*)d_in[5];   // [3,256]
    const float* gamma = (const float*)d_in[6];   // [3,256]
    const float* beta  = (const float*)d_in[7];   // [3,256]
    const float* Wout  = (const float*)d_in[8];   // [256,1]
    const float* bout  = (const float*)d_in[9];   // [1]
    float* out = (float*)d_out;

    float* Ha; float* Hb;
    cudaGetSymbolAddress((void**)&Ha, g_Ha);
    cudaGetSymbolAddress((void**)&Hb, g_Hb);

    k_minmax<<<IND, 256>>>(x);
    k_z<<<(BATCHN * IND + 255) / 256, 256>>>(x);
    k_sort<<<DDEPTH * IND, GRIDN>>>(grids);
    k_table<<<DDEPTH * IND, HIDN>>>(fs);
    k_tmap<<<DDEPTH * IND, 256>>>();
    k_main<<<BATCHN / 4, 256>>>(ds);

    k_zstat<<<1, HIDN>>>();
    // layer 0: Ha(raw) -> Hb
    k_gemm<<<BATCHN / 16, 256>>>(mlpW + 0 * HIDN * HIDN, mlpb + 0 * HIDN, Ha, Hb, 0);
    k_bnfin<<<1, HIDN>>>(gamma + 0 * HIDN, beta + 0 * HIDN);
    // layer 1: bn0+gelu(Hb) -> Ha
    k_gemm<<<BATCHN / 16, 256>>>(mlpW + 1 * HIDN * HIDN, mlpb + 1 * HIDN, Hb, Ha, 1);
    k_bnfin<<<1, HIDN>>>(gamma + 1 * HIDN, beta + 1 * HIDN);
    // layer 2: bn1+gelu(Ha) -> Hb
    k_gemm<<<BATCHN / 16, 256>>>(mlpW + 2 * HIDN * HIDN, mlpb + 2 * HIDN, Ha, Hb, 1);
    k_bnfin<<<1, HIDN>>>(gamma + 2 * HIDN, beta + 2 * HIDN);
    // final: bn2+gelu(Hb) @ Wout + bout
    k_final<<<BATCHN / 8, 256>>>(Wout, bout, out);
}